// round 7
// baseline (speedup 1.0000x reference)
#include <cuda_runtime.h>
#include <math.h>
#include <stdint.h>

#define NB   4
#define HW   4096
#define DH   128
#define NTOK 4096

// Scratch (device globals; allocation-free). fp8 now; arrays oversized is fine.
// Q: A-frag m16n8k32 [b][mt(256)][ks(4)][lane(32)][4 u32]          (512 KB/b)
// K: paired B-frag   [b][tile(64)][ntp(4)][ks(4)][lane(32)][4 u32] (8 KB/tile)
// V: paired B-frag   [b][tile(64)][dtp(8)][u(2)][lane(32)][4 u32]  (8 KB/tile)
//    with key order permuted (pi) so P C-frags pack directly into A-frags.
// O: plain fp32 [b][n][d] (raw-view == NCHW flat)
__device__ uint32_t g_Q[NB * 131072];
__device__ uint32_t g_K[NB * 131072];
__device__ uint32_t g_V[NB * 131072];
__device__ float    g_O[NB * NTOK * DH];

// log2(e)/sqrt(128): Q pre-scale so softmax runs in exp2 domain.
#define QSCALE (0.08838834764831845f * 1.4426950408889634f)

__device__ __forceinline__ float ex2f(float x) {
    float y; asm("ex2.approx.f32 %0, %1;" : "=f"(y) : "f"(x)); return y;
}
__device__ __forceinline__ uint32_t pack4_e4m3(float f0, float f1, float f2, float f3) {
    uint32_t r;
    asm("{\n\t.reg .b16 lo, hi;\n\t"
        "cvt.rn.satfinite.e4m3x2.f32 lo, %2, %1;\n\t"
        "cvt.rn.satfinite.e4m3x2.f32 hi, %4, %3;\n\t"
        "mov.b32 %0, {lo, hi};\n\t}"
        : "=r"(r) : "f"(f0), "f"(f1), "f"(f2), "f"(f3));
    return r;
}
__device__ __forceinline__ uint32_t e4m3_byte(float x) {
    uint16_t h;
    asm("{\n\t.reg .b16 t;\n\tcvt.rn.satfinite.e4m3x2.f32 t, %1, %1;\n\tmov.b16 %0, t;\n\t}"
        : "=h"(h) : "f"(x));
    return (uint32_t)(h & 0xFF);
}
__device__ __forceinline__ void mma_e4m3(float* d,
    uint32_t a0, uint32_t a1, uint32_t a2, uint32_t a3, uint32_t b0, uint32_t b1)
{
    asm volatile(
        "mma.sync.aligned.m16n8k32.row.col.f32.e4m3.e4m3.f32 "
        "{%0,%1,%2,%3},{%4,%5,%6,%7},{%8,%9},{%0,%1,%2,%3};"
        : "+f"(d[0]), "+f"(d[1]), "+f"(d[2]), "+f"(d[3])
        : "r"(a0), "r"(a1), "r"(a2), "r"(a3), "r"(b0), "r"(b1));
}
__device__ __forceinline__ void mma_e4m3_init(float* d,
    uint32_t a0, uint32_t a1, uint32_t a2, uint32_t a3, uint32_t b0, uint32_t b1)
{
    asm volatile(
        "mma.sync.aligned.m16n8k32.row.col.f32.e4m3.e4m3.f32 "
        "{%0,%1,%2,%3},{%4,%5,%6,%7},{%8,%9},{%10,%11,%12,%13};"
        : "=f"(d[0]), "=f"(d[1]), "=f"(d[2]), "=f"(d[3])
        : "r"(a0), "r"(a1), "r"(a2), "r"(a3), "r"(b0), "r"(b1),
          "f"(0.f), "f"(0.f), "f"(0.f), "f"(0.f));
}
__device__ __forceinline__ void cp_async16(void* smem_dst, const void* gmem_src) {
    uint32_t s = (uint32_t)__cvta_generic_to_shared(smem_dst);
    asm volatile("cp.async.cg.shared.global [%0], [%1], 16;\n" :: "r"(s), "l"(gmem_src));
}
#define CP_COMMIT() asm volatile("cp.async.commit_group;\n" ::: "memory")
template<int N> __device__ __forceinline__ void cp_wait() {
    asm volatile("cp.async.wait_group %0;\n" :: "n"(N) : "memory");
}

// ---------------------------------------------------------------------------
// Merged Q/K/V 1x1-conv projection. blockIdx.z = b*3 + m (m: 0=Q, 1=K, 2=V).
// Writes fp8 fragment-image layouts consumed by flash_kernel.
// ---------------------------------------------------------------------------
__global__ __launch_bounds__(256) void proj_qkv(
    const float* __restrict__ xu, const float* __restrict__ xl,
    const float* __restrict__ wq, const float* __restrict__ bq,
    const float* __restrict__ wk, const float* __restrict__ bk,
    const float* __restrict__ wv, const float* __restrict__ bv,
    uint32_t* __restrict__ Qo, uint32_t* __restrict__ Ko,
    uint32_t* __restrict__ Vo)
{
    __shared__ float xs[16][256];
    __shared__ float ws[32][16];

    const int m  = blockIdx.z % 3;
    const int b  = blockIdx.z / 3;
    const int CIN = (m == 0) ? 64 : 128;
    const float* x    = (m == 0) ? (xu + (size_t)b * 64 * HW)
                                 : (xl + (size_t)b * 128 * HW);
    const float* w    = (m == 0) ? wq : (m == 1) ? wk : wv;
    const float* bias = (m == 0) ? bq : (m == 1) ? bk : bv;

    const int c0 = blockIdx.y * 32, s0 = blockIdx.x * 256;
    const int tid = threadIdx.x, tx = tid & 63, ty = tid >> 6;

    float acc[8][4];
#pragma unroll
    for (int i = 0; i < 8; i++)
#pragma unroll
        for (int j = 0; j < 4; j++) acc[i][j] = 0.f;

    for (int k0 = 0; k0 < CIN; k0 += 16) {
        __syncthreads();
#pragma unroll
        for (int t = 0; t < 4; t++) {
            int f = tid + 256 * t, r = f >> 6, c4 = (f & 63) << 2;
            *(float4*)&xs[r][c4] = *(const float4*)(x + (size_t)(k0 + r) * HW + s0 + c4);
        }
#pragma unroll
        for (int t = 0; t < 2; t++) {
            int f = tid + 256 * t;
            ws[f >> 4][f & 15] = w[(size_t)(c0 + (f >> 4)) * CIN + k0 + (f & 15)];
        }
        __syncthreads();
#pragma unroll
        for (int k = 0; k < 16; k++) {
            float4 xv = *(float4*)&xs[k][tx << 2];
#pragma unroll
            for (int cc = 0; cc < 8; cc++) {
                float wv = ws[ty * 8 + cc][k];
                acc[cc][0] = fmaf(wv, xv.x, acc[cc][0]);
                acc[cc][1] = fmaf(wv, xv.y, acc[cc][1]);
                acc[cc][2] = fmaf(wv, xv.z, acc[cc][2]);
                acc[cc][3] = fmaf(wv, xv.w, acc[cc][3]);
            }
        }
    }

#pragma unroll
    for (int cc = 0; cc < 8; cc++) {
        const int c = c0 + ty * 8 + cc;
        const float bv_ = bias[c];
        const int s = s0 + (tx << 2);
        float v0 = acc[cc][0] + bv_, v1 = acc[cc][1] + bv_;
        float v2 = acc[cc][2] + bv_, v3 = acc[cc][3] + bv_;
        const int d0 = s & 127;            // channel-dim (multiple of 4)
        const int n  = c * 32 + (s >> 7);  // token
        const int ks = d0 >> 5, dd = d0 & 31;
        const int h = dd >> 4, t = (dd >> 2) & 3;   // k-half, quad-thread

        if (m == 0) {          // Q A-frag, pre-scaled
            int mt = n >> 4, r = n & 15;
            int g = r & 7, hi = r >> 3;
            size_t idx = (((size_t)b * 256 + mt) * 4 + ks) * 128
                       + (g * 4 + t) * 4 + hi + 2 * h;
            Qo[idx] = pack4_e4m3(v0 * QSCALE, v1 * QSCALE, v2 * QSCALE, v3 * QSCALE);
        } else if (m == 1) {   // K paired B-frag
            int tile = n >> 6, j = n & 63;
            int nt = j >> 3, g = j & 7, ntp = nt >> 1, odd = nt & 1;
            size_t idx = (size_t)b * 131072 + (size_t)tile * 2048
                       + ((ntp * 4 + ks) * 32 + g * 4 + t) * 4 + odd * 2 + h;
            Ko[idx] = pack4_e4m3(v0, v1, v2, v3);
        } else {               // V paired B-frag with pi-permuted key order
            int tile = n >> 6, j = n & 63;
            int u  = j >> 5, jl = j & 31;
            int hv = jl >> 4, cpv = (jl >> 3) & 1, tv = (jl >> 1) & 3, c1 = jl & 1;
            int cv = cpv * 2 + c1;
            char* base = (char*)Vo + (size_t)b * 524288 + (size_t)tile * 8192;
            float vv[4] = {v0, v1, v2, v3};
#pragma unroll
            for (int q4 = 0; q4 < 4; q4++) {
                int d = d0 + q4;
                int dtp = d >> 4, odd = (d >> 3) & 1, g = d & 7;
                base[(((dtp * 2 + u) * 32 + g * 4 + tv) * 4 + odd * 2 + hv) * 4 + cv] =
                    (char)e4m3_byte(vv[q4]);
            }
        }
    }
}

// ---------------------------------------------------------------------------
// fp8 m16n8k32 flash. BM=64/CTA (4 warps x 16 rows), BN=64, D=128.
// 128 threads/CTA -> 2+ CTAs/SM (de-lockstepped). No-max exp2 softmax.
// ---------------------------------------------------------------------------
__global__ __launch_bounds__(128) void flash_kernel(
    const uint4* __restrict__ Qg, const char* __restrict__ Kg_,
    const char* __restrict__ Vg_, float* __restrict__ O)
{
    extern __shared__ uint32_t sm[];   // 4 stages x (K 2048 u32 + V 2048 u32)

    const int b = blockIdx.y, bx = blockIdx.x;
    const int tid = threadIdx.x, w = tid >> 5, lane = tid & 31;
    const int g = lane >> 2, t = lane & 3;

    const char* Kg = Kg_ + (size_t)b * 524288;
    const char* Vg = Vg_ + (size_t)b * 524288;

    auto issueKV = [&](int i) {
        uint32_t st = (uint32_t)(i & 3) * 4096;
        const char* kg = Kg + (size_t)i * 8192;
        const char* vg = Vg + (size_t)i * 8192;
#pragma unroll
        for (int tt = 0; tt < 4; tt++) {
            int f = (tid + 128 * tt) * 16;
            cp_async16((char*)(sm + st) + f, kg + f);
        }
#pragma unroll
        for (int tt = 0; tt < 4; tt++) {
            int f = (tid + 128 * tt) * 16;
            cp_async16((char*)(sm + st + 2048) + f, vg + f);
        }
        CP_COMMIT();
    };
    issueKV(0); issueKV(1); issueKV(2);

    // Q A-frags (4 k32 chunks) -> registers
    uint4 q[4];
    {
        const uint4* qp = Qg + ((size_t)(b * 256 + bx * 4 + w) * 4) * 32 + lane;
#pragma unroll
        for (int ks = 0; ks < 4; ks++) q[ks] = qp[ks * 32];
    }

    float o[16][4];
#pragma unroll
    for (int dt = 0; dt < 16; dt++)
#pragma unroll
        for (int j = 0; j < 4; j++) o[dt][j] = 0.f;
    float ls0 = 0.f, ls1 = 0.f;
    float sf[8][4];

    // S(0)
    cp_wait<2>();
    __syncthreads();
#pragma unroll
    for (int ks = 0; ks < 4; ks++) {
#pragma unroll
        for (int ntp = 0; ntp < 4; ntp++) {
            uint4 kb = *(const uint4*)(sm + (ntp * 4 + ks) * 128 + lane * 4);
            if (ks == 0) {
                mma_e4m3_init(sf[ntp * 2],     q[ks].x, q[ks].y, q[ks].z, q[ks].w, kb.x, kb.y);
                mma_e4m3_init(sf[ntp * 2 + 1], q[ks].x, q[ks].y, q[ks].z, q[ks].w, kb.z, kb.w);
            } else {
                mma_e4m3(sf[ntp * 2],     q[ks].x, q[ks].y, q[ks].z, q[ks].w, kb.x, kb.y);
                mma_e4m3(sf[ntp * 2 + 1], q[ks].x, q[ks].y, q[ks].z, q[ks].w, kb.z, kb.w);
            }
        }
    }

    for (int i = 0; i < 64; i++) {
        cp_wait<1>();
        __syncthreads();
        if (i + 3 < 64) issueKV(i + 3); else CP_COMMIT();

        const uint32_t* ksb = sm + (uint32_t)((i + 1) & 3) * 4096;
        const uint32_t* vsb = sm + (uint32_t)(i & 3) * 4096 + 2048;

        // ---- softmax (no max, exp2 domain) + fp8 P A-frags (zero shuffles) ----
        uint32_t pa[2][4];
#pragma unroll
        for (int u = 0; u < 2; u++) {
            float e[4][4];
#pragma unroll
            for (int k = 0; k < 4; k++) {
                e[k][0] = ex2f(sf[4*u + k][0]); e[k][1] = ex2f(sf[4*u + k][1]);
                e[k][2] = ex2f(sf[4*u + k][2]); e[k][3] = ex2f(sf[4*u + k][3]);
                ls0 += e[k][0] + e[k][1];
                ls1 += e[k][2] + e[k][3];
            }
            pa[u][0] = pack4_e4m3(e[0][0], e[0][1], e[1][0], e[1][1]);
            pa[u][1] = pack4_e4m3(e[0][2], e[0][3], e[1][2], e[1][3]);
            pa[u][2] = pack4_e4m3(e[2][0], e[2][1], e[3][0], e[3][1]);
            pa[u][3] = pack4_e4m3(e[2][2], e[2][3], e[3][2], e[3][3]);
        }

        // ---- S(i+1) ----
        if (i < 63) {
#pragma unroll
            for (int ks = 0; ks < 4; ks++) {
#pragma unroll
                for (int ntp = 0; ntp < 4; ntp++) {
                    uint4 kb = *(const uint4*)(ksb + (ntp * 4 + ks) * 128 + lane * 4);
                    if (ks == 0) {
                        mma_e4m3_init(sf[ntp * 2],     q[ks].x, q[ks].y, q[ks].z, q[ks].w, kb.x, kb.y);
                        mma_e4m3_init(sf[ntp * 2 + 1], q[ks].x, q[ks].y, q[ks].z, q[ks].w, kb.z, kb.w);
                    } else {
                        mma_e4m3(sf[ntp * 2],     q[ks].x, q[ks].y, q[ks].z, q[ks].w, kb.x, kb.y);
                        mma_e4m3(sf[ntp * 2 + 1], q[ks].x, q[ks].y, q[ks].z, q[ks].w, kb.z, kb.w);
                    }
                }
            }
        }

        // ---- PV(i): o += P @ V (keys pi-permuted to match pa packing) ----
#pragma unroll
        for (int u = 0; u < 2; u++) {
#pragma unroll
            for (int dtp = 0; dtp < 8; dtp++) {
                uint4 vv = *(const uint4*)(vsb + (dtp * 2 + u) * 128 + lane * 4);
                mma_e4m3(o[dtp * 2],     pa[u][0], pa[u][1], pa[u][2], pa[u][3], vv.x, vv.y);
                mma_e4m3(o[dtp * 2 + 1], pa[u][0], pa[u][1], pa[u][2], pa[u][3], vv.z, vv.w);
            }
        }
    }

    // ---- epilogue ----
    ls0 += __shfl_xor_sync(0xffffffffu, ls0, 1);
    ls0 += __shfl_xor_sync(0xffffffffu, ls0, 2);
    ls1 += __shfl_xor_sync(0xffffffffu, ls1, 1);
    ls1 += __shfl_xor_sync(0xffffffffu, ls1, 2);
    const float inv0 = 1.0f / ls0, inv1 = 1.0f / ls1;

    float* Ob = O + ((size_t)(b * NTOK) + bx * 64 + w * 16) * DH;
#pragma unroll
    for (int dt = 0; dt < 16; dt++) {
        float2 r0 = make_float2(o[dt][0] * inv0, o[dt][1] * inv0);
        float2 r1 = make_float2(o[dt][2] * inv1, o[dt][3] * inv1);
        *(float2*)(Ob + g * DH + dt * 8 + 2 * t)       = r0;
        *(float2*)(Ob + (g + 8) * DH + dt * 8 + 2 * t) = r1;
    }
}

// ---------------------------------------------------------------------------
// Final 1x1 conv: out = wo @ O + bo + x_lower   (fp32)
// ---------------------------------------------------------------------------
__global__ __launch_bounds__(256) void proj_out(
    const float* __restrict__ x, const float* __restrict__ w,
    const float* __restrict__ bias, const float* __restrict__ res,
    float* __restrict__ out)
{
    __shared__ float xs[16][256];
    __shared__ float ws[32][16];
    const int b = blockIdx.z, c0 = blockIdx.y * 32, s0 = blockIdx.x * 256;
    const int tid = threadIdx.x, tx = tid & 63, ty = tid >> 6;

    float acc[8][4];
#pragma unroll
    for (int i = 0; i < 8; i++)
#pragma unroll
        for (int j = 0; j < 4; j++) acc[i][j] = 0.f;

    for (int k0 = 0; k0 < 128; k0 += 16) {
        __syncthreads();
#pragma unroll
        for (int t = 0; t < 4; t++) {
            int f = tid + 256 * t, r = f >> 6, c4 = (f & 63) << 2;
            *(float4*)&xs[r][c4] =
                *(const float4*)(x + ((size_t)b * 128 + k0 + r) * HW + s0 + c4);
        }
#pragma unroll
        for (int t = 0; t < 2; t++) {
            int f = tid + 256 * t;
            ws[f >> 4][f & 15] = w[(size_t)(c0 + (f >> 4)) * 128 + k0 + (f & 15)];
        }
        __syncthreads();
#pragma unroll
        for (int k = 0; k < 16; k++) {
            float4 xv = *(float4*)&xs[k][tx << 2];
#pragma unroll
            for (int cc = 0; cc < 8; cc++) {
                float wv = ws[ty * 8 + cc][k];
                acc[cc][0] = fmaf(wv, xv.x, acc[cc][0]);
                acc[cc][1] = fmaf(wv, xv.y, acc[cc][1]);
                acc[cc][2] = fmaf(wv, xv.z, acc[cc][2]);
                acc[cc][3] = fmaf(wv, xv.w, acc[cc][3]);
            }
        }
    }

#pragma unroll
    for (int cc = 0; cc < 8; cc++) {
        const int c = c0 + ty * 8 + cc;
        const float bv = bias[c];
        const int s = s0 + (tx << 2);
        float4 rv = *(const float4*)(res + ((size_t)b * DH + c) * HW + s);
        float4 o;
        o.x = acc[cc][0] + bv + rv.x; o.y = acc[cc][1] + bv + rv.y;
        o.z = acc[cc][2] + bv + rv.z; o.w = acc[cc][3] + bv + rv.w;
        *(float4*)(out + ((size_t)b * DH + c) * HW + s) = o;
    }
}

static const int FLASH_SMEM = 4 * 4096 * 4;  // 64 KB

extern "C" void kernel_launch(void* const* d_in, const int* in_sizes, int n_in,
                              void* d_out, int out_size)
{
    const float* x_upper = (const float*)d_in[0];
    const float* x_lower = (const float*)d_in[1];
    const float* wq = (const float*)d_in[2];
    const float* bq = (const float*)d_in[3];
    const float* wk = (const float*)d_in[4];
    const float* bk = (const float*)d_in[5];
    const float* wv = (const float*)d_in[6];
    const float* bv = (const float*)d_in[7];
    const float* wo = (const float*)d_in[8];
    const float* bo = (const float*)d_in[9];
    float* out = (float*)d_out;

    uint32_t *Qp, *Kp, *Vp; float* Op;
    cudaGetSymbolAddress((void**)&Qp, g_Q);
    cudaGetSymbolAddress((void**)&Kp, g_K);
    cudaGetSymbolAddress((void**)&Vp, g_V);
    cudaGetSymbolAddress((void**)&Op, g_O);

    cudaFuncSetAttribute(flash_kernel,
                         cudaFuncAttributeMaxDynamicSharedMemorySize, FLASH_SMEM);

    proj_qkv<<<dim3(16, 4, 12), 256>>>(x_upper, x_lower, wq, bq, wk, bk, wv, bv,
                                       Qp, Kp, Vp);

    flash_kernel<<<dim3(64, NB), 128, FLASH_SMEM>>>(
        (const uint4*)Qp, (const char*)Kp, (const char*)Vp, Op);

    proj_out<<<dim3(16, 4, 4), 256>>>(Op, wo, bo, x_lower, out);
}